// round 14
// baseline (speedup 1.0000x reference)
#include <cuda_runtime.h>
#include <cuda_bf16.h>
#include <cuda_fp16.h>
#include <cstdint>

#define NN     100000
#define NE     1600000
#define NREGN  50000
#define NN_PAD 100096   /* 782*128 */
#define NREG_PAD 50048  /* 391*128 */
#define NPATH  4
#define ETAB   200000

// ---------------- scratch (device globals; no allocation allowed) ----------
__device__ __align__(16) __half g_X1h[(size_t)NPATH * NN_PAD * 128];
__device__ __align__(16) __half g_Mh [(size_t)NPATH * NN_PAD * 128];
__device__ __align__(16) __half g_E16[(size_t)ETAB * 128];
__device__ __align__(16) float  g_SEM[(size_t)NPATH * NREG_PAD * 128];
__device__ int   g_eids32[NPATH * NN];
__device__ int   g_deg[NPATH * NN];
__device__ int   g_rowstart[NPATH * (NN + 1)];
__device__ int   g_cursor[NPATH * NN];
__device__ int   g_col[(size_t)NPATH * NE];
__device__ int   g_bsum[100];
__device__ int   g_boff[100];
__device__ float g_q[512];
__device__ int   g_is64;

// ---------------- dtype detection (int64 vs int32 edge indices) ------------
__global__ void detect_kernel(const unsigned* __restrict__ ei) {
    __shared__ unsigned sh[256];
    unsigned o = 0;
    for (int i = threadIdx.x; i < 4096; i += 256) o |= ei[2 * i + 1];
    sh[threadIdx.x] = o;
    __syncthreads();
    for (int off = 128; off > 0; off >>= 1) {
        if (threadIdx.x < off) sh[threadIdx.x] |= sh[threadIdx.x + off];
        __syncthreads();
    }
    if (threadIdx.x == 0) g_is64 = (sh[0] == 0u) ? 1 : 0;
}

__device__ __forceinline__ long long load_idx(const void* base, long long i) {
    return g_is64 ? ((const long long*)base)[i]
                  : (long long)((const int*)base)[i];
}

// ---------------- eids -> int32 table --------------------------------------
__global__ void conv_eids_kernel(const void* __restrict__ eids) {
    int i = blockIdx.x * 256 + threadIdx.x;
    if (i < NPATH * NN) g_eids32[i] = (int)load_idx(eids, i);
}

// ---------------- E -> fp16 table ------------------------------------------
__global__ void conv_E_kernel(const float* __restrict__ E) {
    size_t i = (size_t)blockIdx.x * 256 + threadIdx.x;   // 25000*256 = ETAB*32
    float4 v = ((const float4*)E)[i];
    __half2 h0 = __floats2half2_rn(v.x, v.y);
    __half2 h1 = __floats2half2_rn(v.z, v.w);
    uint2 pk;
    pk.x = *(unsigned*)&h0;
    pk.y = *(unsigned*)&h1;
    ((uint2*)g_E16)[i] = pk;
}

// ---------------- CSR build ------------------------------------------------
__global__ void zero_deg_kernel() {
    int i = blockIdx.x * 256 + threadIdx.x;
    if (i < NPATH * NN) g_deg[i] = 0;
}

__global__ void count_all_kernel(const void* __restrict__ ei) {
    long long e = (long long)blockIdx.x * 256 + threadIdx.x; // 25000*256
    int p = (int)(e / NE);
    long long le = e % NE;
    int d = (int)load_idx(ei, ((long long)p * 2 + 1) * NE + le);
    atomicAdd(&g_deg[p * NN + d], 1);
}

#define SBLK 4096
#define BPP  25      /* blocks per path: 25*4096 >= NN */

__global__ void scan_reduce_kernel() {
    int blk = blockIdx.x;              // 100
    int p = blk / BPP, lb = blk % BPP;
    int t = threadIdx.x;               // 256
    int base = lb * SBLK;
    int s = 0;
    for (int i = t; i < SBLK; i += 256) {
        int idx = base + i;
        if (idx < NN) s += g_deg[p * NN + idx];
    }
    __shared__ int sh[256];
    sh[t] = s;
    __syncthreads();
    for (int o = 128; o > 0; o >>= 1) {
        if (t < o) sh[t] += sh[t + o];
        __syncthreads();
    }
    if (t == 0) g_bsum[blk] = sh[0];
}

__global__ void scan_off_kernel() {
    int p = threadIdx.x;
    if (p < NPATH) {
        int run = 0;
        for (int i = 0; i < BPP; i++) {
            g_boff[p * BPP + i] = run;
            run += g_bsum[p * BPP + i];
        }
    }
}

__global__ void scan_write_kernel() {
    int blk = blockIdx.x;
    int p = blk / BPP, lb = blk % BPP;
    int t = threadIdx.x;
    int base = lb * SBLK + t * 16;
    int v[16];
    int s = 0;
#pragma unroll
    for (int i = 0; i < 16; i++) {
        int idx = base + i;
        v[i] = (idx < NN) ? g_deg[p * NN + idx] : 0;
        s += v[i];
    }
    __shared__ int sh[256];
    sh[t] = s;
    __syncthreads();
    for (int o = 1; o < 256; o <<= 1) {
        int u = (t >= o) ? sh[t - o] : 0;
        __syncthreads();
        sh[t] += u;
        __syncthreads();
    }
    int run = g_boff[blk] + sh[t] - s;   // exclusive prefix
#pragma unroll
    for (int i = 0; i < 16; i++) {
        int idx = base + i;
        if (idx < NN) {
            g_rowstart[p * (NN + 1) + idx] = run;
            g_cursor[p * NN + idx] = run;
            run += v[i];
        }
    }
    if (t == 0 && lb == 0) g_rowstart[p * (NN + 1) + NN] = NE;
}

// per-path scatter (grid NE/256)
__global__ void scatter_kernel(const void* __restrict__ ei, int p) {
    long long le = (long long)blockIdx.x * 256 + threadIdx.x;
    int s = (int)load_idx(ei, ((long long)p * 2 + 0) * NE + le);
    int d = (int)load_idx(ei, ((long long)p * 2 + 1) * NE + le);
    int pos = atomicAdd(&g_cursor[p * NN + d], 1);
    g_col[(size_t)p * NE + pos] = s;
}

// ---------------- layer-1 mean aggregation (fp16 E rows, one path) ---------
__global__ void agg1_kernel(int p) {
    long long gid = (long long)blockIdx.x * 256 + threadIdx.x;
    long long w = gid >> 5;
    int lane = (int)(gid & 31);
    if (w >= NN) return;
    int n = (int)w;
    __half* Mp = g_Mh + (size_t)p * NN_PAD * 128;
    const int* rs = g_rowstart + p * (NN + 1);
    const int* col = g_col + (size_t)p * NE;
    const int* eid = g_eids32 + p * NN;
    int s = rs[n], e = rs[n + 1];
    int cnt = e - s;
    float x0 = 0.f, x1 = 0.f, x2 = 0.f, x3 = 0.f;
    for (int base = 0; base < cnt; base += 32) {
        int k = base + lane;
        int myEid = 0;
        if (k < cnt) myEid = eid[col[s + k]];
        int m = min(32, cnt - base);
        for (int t = 0; t < m; t++) {
            int ee = __shfl_sync(0xffffffffu, myEid, t);
            uint2 raw = ((const uint2*)(g_E16 + (size_t)ee * 128))[lane];
            float2 a = __half22float2(*(__half2*)&raw.x);
            float2 b = __half22float2(*(__half2*)&raw.y);
            x0 += a.x; x1 += a.y; x2 += b.x; x3 += b.y;
        }
    }
    float inv = 1.f / (float)(cnt > 0 ? cnt : 1);
    __half2 h0 = __floats2half2_rn(x0 * inv, x1 * inv);
    __half2 h1 = __floats2half2_rn(x2 * inv, x3 * inv);
    uint2 pk;
    pk.x = *(unsigned*)&h0;
    pk.y = *(unsigned*)&h1;
    ((uint2*)Mp)[(size_t)n * 32 + lane] = pk;
}

// ---------------- layer-2 mean aggregation (fp16 X1 rows, one path) --------
__global__ void agg2_kernel(int p) {
    long long gid = (long long)blockIdx.x * 256 + threadIdx.x;
    long long w = gid >> 5;
    int lane = (int)(gid & 31);
    if (w >= NREGN) return;
    int n = (int)w;
    const __half* Xh = g_X1h + (size_t)p * NN_PAD * 128;
    __half* Mp = g_Mh + (size_t)p * NN_PAD * 128;
    const int* rs = g_rowstart + p * (NN + 1);
    const int* col = g_col + (size_t)p * NE;
    int s = rs[n], e = rs[n + 1];
    int cnt = e - s;
    float x0 = 0.f, x1 = 0.f, x2 = 0.f, x3 = 0.f;
    for (int base = 0; base < cnt; base += 32) {
        int k = base + lane;
        int mySrc = (k < cnt) ? col[s + k] : 0;
        int m = min(32, cnt - base);
        for (int t = 0; t < m; t++) {
            int src = __shfl_sync(0xffffffffu, mySrc, t);
            uint2 raw = ((const uint2*)(Xh + (size_t)src * 128))[lane];
            float2 a = __half22float2(*(__half2*)&raw.x);
            float2 b = __half22float2(*(__half2*)&raw.y);
            x0 += a.x; x1 += a.y; x2 += b.x; x3 += b.y;
        }
    }
    float inv = 1.f / (float)(cnt > 0 ? cnt : 1);
    __half2 h0 = __floats2half2_rn(x0 * inv, x1 * inv);
    __half2 h1 = __floats2half2_rn(x2 * inv, x3 * inv);
    uint2 pk;
    pk.x = *(unsigned*)&h0;
    pk.y = *(unsigned*)&h1;
    ((uint2*)Mp)[(size_t)n * 32 + lane] = pk;
}

// ============ f16 mma GEMM: C = relu([X|M] (Mx256) @ W (256x128) + b) ======
// Single-product f16, A operands stored fp16. One path per launch.
// Block tile 128x128, 8 warps (4x2), warp tile 32x64, m16n8k16 fragments.
// BK=32 (8 chunks), 3-stage cp.async pipeline, ldmatrix A-fragment loads.

#define SM_WH   0
#define SM_A    65536                 /* 3 stages x 10240 (128 rows x 80 B) */
#define SM_BIAS 96256
#define SMEM_TOTAL 96768

#define A_ROW_STRIDE 80

#define CP_ASYNC16(saddr, gptr) \
    asm volatile("cp.async.ca.shared.global [%0], [%1], 16;" \
                 :: "r"(saddr), "l"(gptr))
#define CP_COMMIT() asm volatile("cp.async.commit_group;" ::: "memory")
#define CP_WAIT2()  asm volatile("cp.async.wait_group 2;" ::: "memory")

#define MMA16816F(c, a, b0_, b1_)                                             \
    asm volatile("mma.sync.aligned.m16n8k16.row.col.f32.f16.f16.f32 "         \
        "{%0,%1,%2,%3}, {%4,%5,%6,%7}, {%8,%9}, {%0,%1,%2,%3};"               \
        : "+f"((c)[0]), "+f"((c)[1]), "+f"((c)[2]), "+f"((c)[3])              \
        : "r"((a)[0]), "r"((a)[1]), "r"((a)[2]), "r"((a)[3]),                 \
          "r"(b0_), "r"(b1_))

#define LDSM_X4(r0_, r1_, r2_, r3_, addr)                                     \
    asm volatile("ldmatrix.sync.aligned.m8n8.x4.shared.b16 {%0,%1,%2,%3}, [%4];" \
        : "=r"(r0_), "=r"(r1_), "=r"(r2_), "=r"(r3_) : "r"(addr))

static __device__ __forceinline__ uint32_t smem_u32(const void* p) {
    uint32_t a;
    asm("{ .reg .u64 t; cvta.to.shared.u64 t, %1; cvt.u32.u64 %0, t; }"
        : "=r"(a) : "l"(p));
    return a;
}

static __device__ __forceinline__ void issue_A(uint32_t sbA, int stage,
                                               const __half* __restrict__ Xb0,
                                               const __half* __restrict__ Xb1,
                                               const __half* __restrict__ Mr0,
                                               const __half* __restrict__ Mr1,
                                               int chunk, int tid) {
    const int seg = tid & 3;
    const int off16 = (chunk & 3) * 32 + seg * 8;
    uint32_t sa = sbA + stage * 10240;
    const int ra = tid >> 2;
    {
        const __half* g = (chunk < 4) ? (Xb0 + off16) : (Mr0 + off16);
        CP_ASYNC16(sa + (uint32_t)(ra * A_ROW_STRIDE + seg * 16), g);
    }
    {
        const __half* g = (chunk < 4) ? (Xb1 + off16) : (Mr1 + off16);
        CP_ASYNC16(sa + (uint32_t)((ra + 64) * A_ROW_STRIDE + seg * 16), g);
    }
}

__global__ void __launch_bounds__(256, 1)
gemm_mma_kernel(int layer, int p,
                const float* __restrict__ W_root, const float* __restrict__ W_rel,
                const float* __restrict__ bias_all, int nTiles) {
    extern __shared__ char sm[];
    uint32_t* WH = (uint32_t*)(sm + SM_WH);
    float*    bsm = (float*)(sm + SM_BIAS);
    const uint32_t sbA = smem_u32(sm) + SM_A;
    const int tid = threadIdx.x, lane = tid & 31, wid = tid >> 5;
    const int rowb = (wid & 3) * 32, colb0 = (wid >> 2) * 64;

    const float* B0 = W_root + ((size_t)p * 2 + layer) * 16384;
    const float* B1 = W_rel  + ((size_t)p * 2 + layer) * 16384;
    const float* bias = bias_all + ((size_t)p * 2 + layer) * 128;
    const __half* X1hp = g_X1h + (size_t)p * NN_PAD * 128;
    const __half* Mhp  = g_Mh  + (size_t)p * NN_PAD * 128;
    __half* X1out = g_X1h + (size_t)p * NN_PAD * 128;
    float*  SEMout = g_SEM + (size_t)p * NREG_PAD * 128;
    const int* eid = g_eids32 + p * NN;

    for (int i = tid; i < 32768; i += 256) {
        int k = i >> 7, n = i & 127;
        float w = (k < 128) ? B0[i] : B1[i - 16384];
        int off = ((((k >> 4) * 128 + n) * 8 + ((k >> 3) & 1) * 4
                    + ((k >> 1) & 3)) << 2) + (k & 1) * 2;
        *(__half*)(sm + SM_WH + off) = __float2half_rn(w);
    }
    if (tid < 128) bsm[tid] = bias[tid];
    __syncthreads();

    const int ra = tid >> 2;
    const int lrow = ((lane >> 3) & 1) * 8 + (lane & 7);
    const int lcol = (lane >> 4) * 16;
    const uint32_t arow_off = (uint32_t)((rowb + lrow) * A_ROW_STRIDE + lcol);

    for (int tile = blockIdx.x; tile < nTiles; tile += gridDim.x) {
        const long long r0 = (long long)tile * 128;

        const __half *Xb0, *Xb1;
        if (layer == 0) {
            long long i0 = r0 + ra, i1 = r0 + ra + 64;
            if (i0 >= NN) i0 = NN - 1;
            if (i1 >= NN) i1 = NN - 1;
            Xb0 = g_E16 + (size_t)eid[i0] * 128;
            Xb1 = g_E16 + (size_t)eid[i1] * 128;
        } else {
            Xb0 = X1hp + (r0 + ra) * 128;
            Xb1 = X1hp + (r0 + ra + 64) * 128;
        }
        const __half* Mr0 = Mhp + (r0 + ra) * 128;
        const __half* Mr1 = Mhp + (r0 + ra + 64) * 128;

        float acc[2][8][4];
#pragma unroll
        for (int mf = 0; mf < 2; mf++)
#pragma unroll
            for (int nf = 0; nf < 8; nf++)
#pragma unroll
                for (int j = 0; j < 4; j++) acc[mf][nf][j] = 0.f;

        issue_A(sbA, 0, Xb0, Xb1, Mr0, Mr1, 0, tid); CP_COMMIT();
        issue_A(sbA, 1, Xb0, Xb1, Mr0, Mr1, 1, tid); CP_COMMIT();
        issue_A(sbA, 2, Xb0, Xb1, Mr0, Mr1, 2, tid); CP_COMMIT();

        for (int c = 0; c < 8; c++) {
            CP_WAIT2();
            __syncthreads();
            const uint32_t abase = sbA + (c % 3) * 10240 + arow_off;

#pragma unroll
            for (int ks = 0; ks < 2; ks++) {
                uint32_t a[2][4];
                LDSM_X4(a[0][0], a[0][1], a[0][2], a[0][3], abase + ks * 32);
                LDSM_X4(a[1][0], a[1][1], a[1][2], a[1][3],
                        abase + 16 * A_ROW_STRIDE + ks * 32);
                const int cb = (c * 2 + ks) * 1024;
#pragma unroll
                for (int nf = 0; nf < 8; nf++) {
                    int bidx = cb + (colb0 + nf * 8 + (lane >> 2)) * 8 + (lane & 3);
                    uint32_t bh0 = WH[bidx], bh1 = WH[bidx + 4];
#pragma unroll
                    for (int mf = 0; mf < 2; mf++) {
                        MMA16816F(acc[mf][nf], a[mf], bh0, bh1);
                    }
                }
            }
            __syncthreads();
            if (c + 3 < 8)
                issue_A(sbA, c % 3, Xb0, Xb1, Mr0, Mr1, c + 3, tid);
            CP_COMMIT();
        }

#pragma unroll
        for (int mf = 0; mf < 2; mf++) {
            long long row = r0 + rowb + mf * 16 + (lane >> 2);
#pragma unroll
            for (int nf = 0; nf < 8; nf++) {
                int col = colb0 + nf * 8 + (lane & 3) * 2;
                float2 bb = *(const float2*)(bsm + col);
                float2 o0, o1;
                o0.x = fmaxf(acc[mf][nf][0] + bb.x, 0.f);
                o0.y = fmaxf(acc[mf][nf][1] + bb.y, 0.f);
                o1.x = fmaxf(acc[mf][nf][2] + bb.x, 0.f);
                o1.y = fmaxf(acc[mf][nf][3] + bb.y, 0.f);
                if (layer == 0) {
                    __half2 h0 = __floats2half2_rn(o0.x, o0.y);
                    __half2 h1 = __floats2half2_rn(o1.x, o1.y);
                    *(__half2*)(X1out + row * 128 + col)       = h0;
                    *(__half2*)(X1out + (row + 8) * 128 + col) = h1;
                } else {
                    *(float2*)(SEMout + row * 128 + col)       = o0;
                    *(float2*)(SEMout + (row + 8) * 128 + col) = o1;
                }
            }
        }
    }
}

// ---------------- query = metapath_emb @ Wq + bq ---------------------------
__global__ void query_kernel(const float* __restrict__ me,
                             const float* __restrict__ Wq,
                             const float* __restrict__ bq) {
    int d = threadIdx.x;
#pragma unroll
    for (int p = 0; p < 4; p++) {
        float s = bq[d];
        for (int k = 0; k < 64; k++) s += me[p * 64 + k] * Wq[k * 128 + d];
        g_q[p * 128 + d] = s;
    }
}

// ---------------- semantic attention combine -------------------------------
__global__ void combine_kernel(float* __restrict__ out) {
    int gid = blockIdx.x * 256 + threadIdx.x;
    int w = gid >> 5, lane = gid & 31;
    if (w >= NREGN) return;
    float4 v[4];
    float dots[4];
#pragma unroll
    for (int p = 0; p < 4; p++) {
        v[p] = ((const float4*)(g_SEM + (size_t)p * NREG_PAD * 128))[(size_t)w * 32 + lane];
        float4 qv = ((const float4*)g_q)[p * 32 + lane];
        float dd = v[p].x * qv.x + v[p].y * qv.y + v[p].z * qv.z + v[p].w * qv.w;
#pragma unroll
        for (int o = 16; o > 0; o >>= 1) dd += __shfl_xor_sync(0xffffffffu, dd, o);
        dots[p] = dd * 0.08838834764831845f;
    }
    float mx = fmaxf(fmaxf(dots[0], dots[1]), fmaxf(dots[2], dots[3]));
    float e0 = __expf(dots[0] - mx), e1 = __expf(dots[1] - mx);
    float e2 = __expf(dots[2] - mx), e3 = __expf(dots[3] - mx);
    float inv = 1.f / (e0 + e1 + e2 + e3);
    float4 o;
    o.x = (e0 * v[0].x + e1 * v[1].x + e2 * v[2].x + e3 * v[3].x) * inv;
    o.y = (e0 * v[0].y + e1 * v[1].y + e2 * v[2].y + e3 * v[3].y) * inv;
    o.z = (e0 * v[0].z + e1 * v[1].z + e2 * v[2].z + e3 * v[3].z) * inv;
    o.w = (e0 * v[0].w + e1 * v[1].w + e2 * v[2].w + e3 * v[3].w) * inv;
    ((float4*)out)[(size_t)w * 32 + lane] = o;
}

// ---------------- host orchestration ---------------------------------------
static inline int cdiv(int a, int b) { return (a + b - 1) / b; }

extern "C" void kernel_launch(void* const* d_in, const int* in_sizes, int n_in,
                              void* d_out, int out_size) {
    const float* E       = (const float*)d_in[0];
    const float* me      = (const float*)d_in[1];
    const float* W_root  = (const float*)d_in[2];
    const float* W_rel   = (const float*)d_in[3];
    const float* b       = (const float*)d_in[4];
    const float* Wq      = (const float*)d_in[5];
    const float* bq      = (const float*)d_in[6];
    const void*  ei      = d_in[7];
    const void*  eids    = d_in[8];
    float* out = (float*)d_out;

    static cudaStream_t s1 = nullptr, s2 = nullptr, s3 = nullptr;
    static cudaEvent_t evDet, evConv, evSc[4], evA1[4], evG0[4], evA2[4], evG1[4];
    static bool init = false;
    if (!init) {
        cudaStreamCreateWithFlags(&s1, cudaStreamNonBlocking);
        cudaStreamCreateWithFlags(&s2, cudaStreamNonBlocking);
        cudaStreamCreateWithFlags(&s3, cudaStreamNonBlocking);
        cudaEventCreateWithFlags(&evDet, cudaEventDisableTiming);
        cudaEventCreateWithFlags(&evConv, cudaEventDisableTiming);
        for (int p = 0; p < 4; p++) {
            cudaEventCreateWithFlags(&evSc[p], cudaEventDisableTiming);
            cudaEventCreateWithFlags(&evA1[p], cudaEventDisableTiming);
            cudaEventCreateWithFlags(&evG0[p], cudaEventDisableTiming);
            cudaEventCreateWithFlags(&evA2[p], cudaEventDisableTiming);
            cudaEventCreateWithFlags(&evG1[p], cudaEventDisableTiming);
        }
        cudaFuncSetAttribute(gemm_mma_kernel,
                             cudaFuncAttributeMaxDynamicSharedMemorySize, SMEM_TOTAL);
        init = true;
    }

    // main: detect; fork conv work to s1
    detect_kernel<<<1, 256>>>((const unsigned*)ei);
    cudaEventRecord(evDet, 0);
    cudaStreamWaitEvent(s1, evDet, 0);
    conv_eids_kernel<<<cdiv(NPATH * NN, 256), 256, 0, s1>>>(eids);
    conv_E_kernel<<<25000, 256, 0, s1>>>(E);
    cudaEventRecord(evConv, s1);

    // main: CSR build
    zero_deg_kernel<<<cdiv(NPATH * NN, 256), 256>>>();
    count_all_kernel<<<NPATH * NE / 256, 256>>>(ei);
    scan_reduce_kernel<<<100, 256>>>();
    scan_off_kernel<<<1, 32>>>();
    scan_write_kernel<<<100, 256>>>();
    for (int p = 0; p < 4; p++) {
        scatter_kernel<<<NE / 256, 256>>>(ei, p);
        cudaEventRecord(evSc[p], 0);
    }
    query_kernel<<<1, 128>>>(me, Wq, bq);

    // s2 (memory stream): agg1 per path
    cudaStreamWaitEvent(s2, evConv, 0);
    for (int p = 0; p < 4; p++) {
        cudaStreamWaitEvent(s2, evSc[p], 0);
        agg1_kernel<<<12500, 256, 0, s2>>>(p);
        cudaEventRecord(evA1[p], s2);
    }
    // s3 (tensor stream): gemm0 per path
    for (int p = 0; p < 4; p++) {
        cudaStreamWaitEvent(s3, evA1[p], 0);
        gemm_mma_kernel<<<148, 256, SMEM_TOTAL, s3>>>(0, p, W_root, W_rel, b,
                                                      NN_PAD / 128);
        cudaEventRecord(evG0[p], s3);
    }
    // s2: agg2 per path (after its gemm0)
    for (int p = 0; p < 4; p++) {
        cudaStreamWaitEvent(s2, evG0[p], 0);
        agg2_kernel<<<6250, 256, 0, s2>>>(p);
        cudaEventRecord(evA2[p], s2);
    }
    // s3: gemm1 per path
    for (int p = 0; p < 4; p++) {
        cudaStreamWaitEvent(s3, evA2[p], 0);
        gemm_mma_kernel<<<148, 256, SMEM_TOTAL, s3>>>(1, p, W_root, W_rel, b,
                                                      NREG_PAD / 128);
        cudaEventRecord(evG1[p], s3);
    }

    // join everything back to main, then combine
    cudaStreamWaitEvent(0, evConv, 0);
    cudaStreamWaitEvent(0, evA2[3], 0);
    for (int p = 0; p < 4; p++) cudaStreamWaitEvent(0, evG1[p], 0);
    combine_kernel<<<cdiv(NREGN, 8), 256>>>(out);
}

// round 15
// speedup vs baseline: 1.0553x; 1.0553x over previous
#include <cuda_runtime.h>
#include <cuda_bf16.h>
#include <cuda_fp16.h>
#include <cstdint>

#define NN     100000
#define NE     1600000
#define NREGN  50000
#define NN_PAD 100096   /* 782*128 */
#define NREG_PAD 50048  /* 391*128 */
#define NPATH  4
#define ETAB   200000

// ---------------- scratch (device globals; no allocation allowed) ----------
__device__ __align__(16) __half g_X1h[(size_t)NPATH * NN_PAD * 128];
__device__ __align__(16) __half g_Mh [(size_t)NPATH * NN_PAD * 128];
__device__ __align__(16) __half g_E16[(size_t)ETAB * 128];
__device__ __align__(16) float  g_SEM[(size_t)NPATH * NREG_PAD * 128];
__device__ int   g_eids32[NPATH * NN];
__device__ int   g_deg[NPATH * NN];
__device__ int   g_rowstart[NPATH * (NN + 1)];
__device__ int   g_cursor[NPATH * NN];
__device__ int   g_col[(size_t)NPATH * NE];
__device__ int   g_bsum[100];
__device__ int   g_boff[100];
__device__ float g_q[512];
__device__ int   g_is64;

// ---------------- dtype detection (int64 vs int32 edge indices) ------------
__global__ void detect_kernel(const unsigned* __restrict__ ei) {
    __shared__ unsigned sh[256];
    unsigned o = 0;
    for (int i = threadIdx.x; i < 4096; i += 256) o |= ei[2 * i + 1];
    sh[threadIdx.x] = o;
    __syncthreads();
    for (int off = 128; off > 0; off >>= 1) {
        if (threadIdx.x < off) sh[threadIdx.x] |= sh[threadIdx.x + off];
        __syncthreads();
    }
    if (threadIdx.x == 0) g_is64 = (sh[0] == 0u) ? 1 : 0;
}

__device__ __forceinline__ long long load_idx(const void* base, long long i) {
    return g_is64 ? ((const long long*)base)[i]
                  : (long long)((const int*)base)[i];
}

// ---------------- eids -> int32 table + deg zeroing (fused) ----------------
__global__ void conv_eids_kernel(const void* __restrict__ eids) {
    int i = blockIdx.x * 256 + threadIdx.x;
    if (i < NPATH * NN) {
        g_eids32[i] = (int)load_idx(eids, i);
        g_deg[i] = 0;
    }
}

// ---------------- E -> fp16 table ------------------------------------------
__global__ void conv_E_kernel(const float* __restrict__ E) {
    size_t i = (size_t)blockIdx.x * 256 + threadIdx.x;   // 25000*256 = ETAB*32
    float4 v = ((const float4*)E)[i];
    __half2 h0 = __floats2half2_rn(v.x, v.y);
    __half2 h1 = __floats2half2_rn(v.z, v.w);
    uint2 pk;
    pk.x = *(unsigned*)&h0;
    pk.y = *(unsigned*)&h1;
    ((uint2*)g_E16)[i] = pk;
}

// ---------------- CSR build (all paths) ------------------------------------
__global__ void count_all_kernel(const void* __restrict__ ei) {
    long long e = (long long)blockIdx.x * 256 + threadIdx.x; // 25000*256
    int p = (int)(e / NE);
    long long le = e % NE;
    int d = (int)load_idx(ei, ((long long)p * 2 + 1) * NE + le);
    atomicAdd(&g_deg[p * NN + d], 1);
}

#define SBLK 4096
#define BPP  25      /* blocks per path: 25*4096 >= NN */

__global__ void scan_reduce_kernel() {
    int blk = blockIdx.x;              // 100
    int p = blk / BPP, lb = blk % BPP;
    int t = threadIdx.x;               // 256
    int base = lb * SBLK;
    int s = 0;
    for (int i = t; i < SBLK; i += 256) {
        int idx = base + i;
        if (idx < NN) s += g_deg[p * NN + idx];
    }
    __shared__ int sh[256];
    sh[t] = s;
    __syncthreads();
    for (int o = 128; o > 0; o >>= 1) {
        if (t < o) sh[t] += sh[t + o];
        __syncthreads();
    }
    if (t == 0) g_bsum[blk] = sh[0];
}

__global__ void scan_off_kernel() {
    int p = threadIdx.x;
    if (p < NPATH) {
        int run = 0;
        for (int i = 0; i < BPP; i++) {
            g_boff[p * BPP + i] = run;
            run += g_bsum[p * BPP + i];
        }
    }
}

__global__ void scan_write_kernel() {
    int blk = blockIdx.x;
    int p = blk / BPP, lb = blk % BPP;
    int t = threadIdx.x;
    int base = lb * SBLK + t * 16;
    int v[16];
    int s = 0;
#pragma unroll
    for (int i = 0; i < 16; i++) {
        int idx = base + i;
        v[i] = (idx < NN) ? g_deg[p * NN + idx] : 0;
        s += v[i];
    }
    __shared__ int sh[256];
    sh[t] = s;
    __syncthreads();
    for (int o = 1; o < 256; o <<= 1) {
        int u = (t >= o) ? sh[t - o] : 0;
        __syncthreads();
        sh[t] += u;
        __syncthreads();
    }
    int run = g_boff[blk] + sh[t] - s;   // exclusive prefix
#pragma unroll
    for (int i = 0; i < 16; i++) {
        int idx = base + i;
        if (idx < NN) {
            g_rowstart[p * (NN + 1) + idx] = run;
            g_cursor[p * NN + idx] = run;
            run += v[i];
        }
    }
    if (t == 0 && lb == 0) g_rowstart[p * (NN + 1) + NN] = NE;
}

__global__ void scatter_all_kernel(const void* __restrict__ ei) {
    long long e = (long long)blockIdx.x * 256 + threadIdx.x;
    int p = (int)(e / NE);
    long long le = e % NE;
    int s = (int)load_idx(ei, ((long long)p * 2 + 0) * NE + le);
    int d = (int)load_idx(ei, ((long long)p * 2 + 1) * NE + le);
    int pos = atomicAdd(&g_cursor[p * NN + d], 1);
    g_col[(size_t)p * NE + pos] = s;
}

// ---------------- layer-1 mean aggregation (fp16 E rows, all paths) --------
__global__ void agg1_kernel() {
    long long gid = (long long)blockIdx.x * 256 + threadIdx.x;
    long long w = gid >> 5;
    int lane = (int)(gid & 31);
    if (w >= (long long)NPATH * NN) return;
    int p = (int)(w / NN), n = (int)(w % NN);
    __half* Mp = g_Mh + (size_t)p * NN_PAD * 128;
    const int* rs = g_rowstart + p * (NN + 1);
    const int* col = g_col + (size_t)p * NE;
    const int* eid = g_eids32 + p * NN;
    int s = rs[n], e = rs[n + 1];
    int cnt = e - s;
    float x0 = 0.f, x1 = 0.f, x2 = 0.f, x3 = 0.f;
    for (int base = 0; base < cnt; base += 32) {
        int k = base + lane;
        int myEid = 0;
        if (k < cnt) myEid = eid[col[s + k]];
        int m = min(32, cnt - base);
        for (int t = 0; t < m; t++) {
            int ee = __shfl_sync(0xffffffffu, myEid, t);
            uint2 raw = ((const uint2*)(g_E16 + (size_t)ee * 128))[lane];
            float2 a = __half22float2(*(__half2*)&raw.x);
            float2 b = __half22float2(*(__half2*)&raw.y);
            x0 += a.x; x1 += a.y; x2 += b.x; x3 += b.y;
        }
    }
    float inv = 1.f / (float)(cnt > 0 ? cnt : 1);
    __half2 h0 = __floats2half2_rn(x0 * inv, x1 * inv);
    __half2 h1 = __floats2half2_rn(x2 * inv, x3 * inv);
    uint2 pk;
    pk.x = *(unsigned*)&h0;
    pk.y = *(unsigned*)&h1;
    ((uint2*)Mp)[(size_t)n * 32 + lane] = pk;
}

// ---------------- layer-2 mean aggregation (fp16 X1 rows, all paths) -------
__global__ void agg2_kernel() {
    long long gid = (long long)blockIdx.x * 256 + threadIdx.x;
    long long w = gid >> 5;
    int lane = (int)(gid & 31);
    if (w >= (long long)NPATH * NREGN) return;
    int p = (int)(w / NREGN), n = (int)(w % NREGN);
    const __half* Xh = g_X1h + (size_t)p * NN_PAD * 128;
    __half* Mp = g_Mh + (size_t)p * NN_PAD * 128;
    const int* rs = g_rowstart + p * (NN + 1);
    const int* col = g_col + (size_t)p * NE;
    int s = rs[n], e = rs[n + 1];
    int cnt = e - s;
    float x0 = 0.f, x1 = 0.f, x2 = 0.f, x3 = 0.f;
    for (int base = 0; base < cnt; base += 32) {
        int k = base + lane;
        int mySrc = (k < cnt) ? col[s + k] : 0;
        int m = min(32, cnt - base);
        for (int t = 0; t < m; t++) {
            int src = __shfl_sync(0xffffffffu, mySrc, t);
            uint2 raw = ((const uint2*)(Xh + (size_t)src * 128))[lane];
            float2 a = __half22float2(*(__half2*)&raw.x);
            float2 b = __half22float2(*(__half2*)&raw.y);
            x0 += a.x; x1 += a.y; x2 += b.x; x3 += b.y;
        }
    }
    float inv = 1.f / (float)(cnt > 0 ? cnt : 1);
    __half2 h0 = __floats2half2_rn(x0 * inv, x1 * inv);
    __half2 h1 = __floats2half2_rn(x2 * inv, x3 * inv);
    uint2 pk;
    pk.x = *(unsigned*)&h0;
    pk.y = *(unsigned*)&h1;
    ((uint2*)Mp)[(size_t)n * 32 + lane] = pk;
}

// ============ f16 mma GEMM: C = relu([X|M] (Mx256) @ W (256x128) + b) ======
// Single-product f16, A operands stored fp16. Batched: p = blockIdx.x & 3.
// Block tile 128x128, 8 warps in 2(M) x 4(N), warp tile 64x32.
// BK=32 (8 chunks), 4-stage cp.async pipeline (ONE barrier per chunk),
// ldmatrix A-fragment loads.

#define SM_WH   0                     /* 65536 */
#define SM_A    65536                 /* 4 stages x 10240 (128 rows x 80 B) */
#define SM_BIAS 106496                /* 128 floats */
#define SMEM_TOTAL 107008

#define A_ROW_STRIDE 80

#define CP_ASYNC16(saddr, gptr) \
    asm volatile("cp.async.ca.shared.global [%0], [%1], 16;" \
                 :: "r"(saddr), "l"(gptr))
#define CP_COMMIT() asm volatile("cp.async.commit_group;" ::: "memory")
#define CP_WAIT2()  asm volatile("cp.async.wait_group 2;" ::: "memory")

#define MMA16816F(c, a, b0_, b1_)                                             \
    asm volatile("mma.sync.aligned.m16n8k16.row.col.f32.f16.f16.f32 "         \
        "{%0,%1,%2,%3}, {%4,%5,%6,%7}, {%8,%9}, {%0,%1,%2,%3};"               \
        : "+f"((c)[0]), "+f"((c)[1]), "+f"((c)[2]), "+f"((c)[3])              \
        : "r"((a)[0]), "r"((a)[1]), "r"((a)[2]), "r"((a)[3]),                 \
          "r"(b0_), "r"(b1_))

#define LDSM_X4(r0_, r1_, r2_, r3_, addr)                                     \
    asm volatile("ldmatrix.sync.aligned.m8n8.x4.shared.b16 {%0,%1,%2,%3}, [%4];" \
        : "=r"(r0_), "=r"(r1_), "=r"(r2_), "=r"(r3_) : "r"(addr))

static __device__ __forceinline__ uint32_t smem_u32(const void* p) {
    uint32_t a;
    asm("{ .reg .u64 t; cvta.to.shared.u64 t, %1; cvt.u32.u64 %0, t; }"
        : "=r"(a) : "l"(p));
    return a;
}

// chunks 0..3: root operand rows; chunks 4..7: M rows
static __device__ __forceinline__ void issue_A(uint32_t sbA, int stage,
                                               const __half* __restrict__ Xb0,
                                               const __half* __restrict__ Xb1,
                                               const __half* __restrict__ Mr0,
                                               const __half* __restrict__ Mr1,
                                               int chunk, int tid) {
    const int seg = tid & 3;
    const int off16 = (chunk & 3) * 32 + seg * 8;
    uint32_t sa = sbA + stage * 10240;
    const int ra = tid >> 2;
    {
        const __half* g = (chunk < 4) ? (Xb0 + off16) : (Mr0 + off16);
        CP_ASYNC16(sa + (uint32_t)(ra * A_ROW_STRIDE + seg * 16), g);
    }
    {
        const __half* g = (chunk < 4) ? (Xb1 + off16) : (Mr1 + off16);
        CP_ASYNC16(sa + (uint32_t)((ra + 64) * A_ROW_STRIDE + seg * 16), g);
    }
}

__global__ void __launch_bounds__(256, 1)
gemm_mma_kernel(int layer,
                const float* __restrict__ W_root, const float* __restrict__ W_rel,
                const float* __restrict__ bias_all, int tilesPerPath) {
    extern __shared__ char sm[];
    uint32_t* WH = (uint32_t*)(sm + SM_WH);
    float*    bsm = (float*)(sm + SM_BIAS);
    const uint32_t sbA = smem_u32(sm) + SM_A;
    const int tid = threadIdx.x, lane = tid & 31, wid = tid >> 5;
    const int mrow = (wid & 1) * 64;        // warp M base (2 warps over M)
    const int ncol = (wid >> 1) * 32;       // warp N base (4 warps over N)

    const int p = blockIdx.x & 3;
    const int lcta = blockIdx.x >> 2;
    const int nCta = gridDim.x >> 2;

    const float* B0 = W_root + ((size_t)p * 2 + layer) * 16384;
    const float* B1 = W_rel  + ((size_t)p * 2 + layer) * 16384;
    const float* bias = bias_all + ((size_t)p * 2 + layer) * 128;
    const __half* X1hp = g_X1h + (size_t)p * NN_PAD * 128;
    const __half* Mhp  = g_Mh  + (size_t)p * NN_PAD * 128;
    __half* X1out = g_X1h + (size_t)p * NN_PAD * 128;
    float*  SEMout = g_SEM + (size_t)p * NREG_PAD * 128;
    const int* eid = g_eids32 + p * NN;

    // ---- convert weights once into fragment-native f16 layout ----
    for (int i = tid; i < 32768; i += 256) {
        int k = i >> 7, n = i & 127;
        float w = (k < 128) ? B0[i] : B1[i - 16384];
        int off = ((((k >> 4) * 128 + n) * 8 + ((k >> 3) & 1) * 4
                    + ((k >> 1) & 3)) << 2) + (k & 1) * 2;
        *(__half*)(sm + SM_WH + off) = __float2half_rn(w);
    }
    if (tid < 128) bsm[tid] = bias[tid];
    __syncthreads();

    const int ra = tid >> 2;
    const int lrow = ((lane >> 3) & 1) * 8 + (lane & 7);
    const int lcol = (lane >> 4) * 16;   // bytes
    const uint32_t arow_off = (uint32_t)((mrow + lrow) * A_ROW_STRIDE + lcol);

    for (int tile = lcta; tile < tilesPerPath; tile += nCta) {
        const long long r0 = (long long)tile * 128;

        const __half *Xb0, *Xb1;
        if (layer == 0) {
            long long i0 = r0 + ra, i1 = r0 + ra + 64;
            if (i0 >= NN) i0 = NN - 1;
            if (i1 >= NN) i1 = NN - 1;
            Xb0 = g_E16 + (size_t)eid[i0] * 128;
            Xb1 = g_E16 + (size_t)eid[i1] * 128;
        } else {
            Xb0 = X1hp + (r0 + ra) * 128;
            Xb1 = X1hp + (r0 + ra + 64) * 128;
        }
        const __half* Mr0 = Mhp + (r0 + ra) * 128;
        const __half* Mr1 = Mhp + (r0 + ra + 64) * 128;

        float acc[4][4][4];
#pragma unroll
        for (int mf = 0; mf < 4; mf++)
#pragma unroll
            for (int nf = 0; nf < 4; nf++)
#pragma unroll
                for (int j = 0; j < 4; j++) acc[mf][nf][j] = 0.f;

        issue_A(sbA, 0, Xb0, Xb1, Mr0, Mr1, 0, tid); CP_COMMIT();
        issue_A(sbA, 1, Xb0, Xb1, Mr0, Mr1, 1, tid); CP_COMMIT();
        issue_A(sbA, 2, Xb0, Xb1, Mr0, Mr1, 2, tid); CP_COMMIT();

        for (int c = 0; c < 8; c++) {
            CP_WAIT2();
            __syncthreads();        // single barrier: safe with 4 stages
            const uint32_t abase = sbA + (c & 3) * 10240 + arow_off;

#pragma unroll
            for (int ks = 0; ks < 2; ks++) {
                uint32_t a[4][4];
#pragma unroll
                for (int mf = 0; mf < 4; mf++) {
                    LDSM_X4(a[mf][0], a[mf][1], a[mf][2], a[mf][3],
                            abase + mf * 16 * A_ROW_STRIDE + ks * 32);
                }
                const int cb = (c * 2 + ks) * 1024;
#pragma unroll
                for (int nf = 0; nf < 4; nf++) {
                    int bidx = cb + (ncol + nf * 8 + (lane >> 2)) * 8 + (lane & 3);
                    uint32_t bh0 = WH[bidx], bh1 = WH[bidx + 4];
#pragma unroll
                    for (int mf = 0; mf < 4; mf++) {
                        MMA16816F(acc[mf][nf], a[mf], bh0, bh1);
                    }
                }
            }
            if (c + 3 < 8)
                issue_A(sbA, (c + 3) & 3, Xb0, Xb1, Mr0, Mr1, c + 3, tid);
            CP_COMMIT();
        }

        // ---- epilogue: bias + relu; layer0 -> f16 X1h, layer1 -> f32 SEM --
        __syncthreads();            // protect stage reuse across tiles
#pragma unroll
        for (int mf = 0; mf < 4; mf++) {
            long long row = r0 + mrow + mf * 16 + (lane >> 2);
#pragma unroll
            for (int nf = 0; nf < 4; nf++) {
                int col = ncol + nf * 8 + (lane & 3) * 2;
                float2 bb = *(const float2*)(bsm + col);
                float2 o0, o1;
                o0.x = fmaxf(acc[mf][nf][0] + bb.x, 0.f);
                o0.y = fmaxf(acc[mf][nf][1] + bb.y, 0.f);
                o1.x = fmaxf(acc[mf][nf][2] + bb.x, 0.f);
                o1.y = fmaxf(acc[mf][nf][3] + bb.y, 0.f);
                if (layer == 0) {
                    __half2 h0 = __floats2half2_rn(o0.x, o0.y);
                    __half2 h1 = __floats2half2_rn(o1.x, o1.y);
                    *(__half2*)(X1out + row * 128 + col)       = h0;
                    *(__half2*)(X1out + (row + 8) * 128 + col) = h1;
                } else {
                    *(float2*)(SEMout + row * 128 + col)       = o0;
                    *(float2*)(SEMout + (row + 8) * 128 + col) = o1;
                }
            }
        }
    }
}

// ---------------- query = metapath_emb @ Wq + bq ---------------------------
__global__ void query_kernel(const float* __restrict__ me,
                             const float* __restrict__ Wq,
                             const float* __restrict__ bq) {
    int d = threadIdx.x;
#pragma unroll
    for (int p = 0; p < 4; p++) {
        float s = bq[d];
        for (int k = 0; k < 64; k++) s += me[p * 64 + k] * Wq[k * 128 + d];
        g_q[p * 128 + d] = s;
    }
}

// ---------------- semantic attention combine -------------------------------
__global__ void combine_kernel(float* __restrict__ out) {
    int gid = blockIdx.x * 256 + threadIdx.x;
    int w = gid >> 5, lane = gid & 31;
    if (w >= NREGN) return;
    float4 v[4];
    float dots[4];
#pragma unroll
    for (int p = 0; p < 4; p++) {
        v[p] = ((const float4*)(g_SEM + (size_t)p * NREG_PAD * 128))[(size_t)w * 32 + lane];
        float4 qv = ((const float4*)g_q)[p * 32 + lane];
        float dd = v[p].x * qv.x + v[p].y * qv.y + v[p].z * qv.z + v[p].w * qv.w;
#pragma unroll
        for (int o = 16; o > 0; o >>= 1) dd += __shfl_xor_sync(0xffffffffu, dd, o);
        dots[p] = dd * 0.08838834764831845f;
    }
    float mx = fmaxf(fmaxf(dots[0], dots[1]), fmaxf(dots[2], dots[3]));
    float e0 = __expf(dots[0] - mx), e1 = __expf(dots[1] - mx);
    float e2 = __expf(dots[2] - mx), e3 = __expf(dots[3] - mx);
    float inv = 1.f / (e0 + e1 + e2 + e3);
    float4 o;
    o.x = (e0 * v[0].x + e1 * v[1].x + e2 * v[2].x + e3 * v[3].x) * inv;
    o.y = (e0 * v[0].y + e1 * v[1].y + e2 * v[2].y + e3 * v[3].y) * inv;
    o.z = (e0 * v[0].z + e1 * v[1].z + e2 * v[2].z + e3 * v[3].z) * inv;
    o.w = (e0 * v[0].w + e1 * v[1].w + e2 * v[2].w + e3 * v[3].w) * inv;
    ((float4*)out)[(size_t)w * 32 + lane] = o;
}

// ---------------- host orchestration ---------------------------------------
static inline int cdiv(int a, int b) { return (a + b - 1) / b; }

extern "C" void kernel_launch(void* const* d_in, const int* in_sizes, int n_in,
                              void* d_out, int out_size) {
    const float* E       = (const float*)d_in[0];
    const float* me      = (const float*)d_in[1];
    const float* W_root  = (const float*)d_in[2];
    const float* W_rel   = (const float*)d_in[3];
    const float* b       = (const float*)d_in[4];
    const float* Wq      = (const float*)d_in[5];
    const float* bq      = (const float*)d_in[6];
    const void*  ei      = d_in[7];
    const void*  eids    = d_in[8];
    float* out = (float*)d_out;

    cudaFuncSetAttribute(gemm_mma_kernel,
                         cudaFuncAttributeMaxDynamicSharedMemorySize, SMEM_TOTAL);

    detect_kernel<<<1, 256>>>((const unsigned*)ei);
    conv_eids_kernel<<<cdiv(NPATH * NN, 256), 256>>>(eids);
    conv_E_kernel<<<25000, 256>>>(E);
    count_all_kernel<<<NPATH * NE / 256, 256>>>(ei);
    scan_reduce_kernel<<<100, 256>>>();
    scan_off_kernel<<<1, 32>>>();
    scan_write_kernel<<<100, 256>>>();
    scatter_all_kernel<<<NPATH * NE / 256, 256>>>(ei);
    query_kernel<<<1, 128>>>(me, Wq, bq);

    agg1_kernel<<<50000, 256>>>();
    gemm_mma_kernel<<<148, 256, SMEM_TOTAL>>>(0, W_root, W_rel, b, NN_PAD / 128);
    agg2_kernel<<<25000, 256>>>();
    gemm_mma_kernel<<<148, 256, SMEM_TOTAL>>>(1, W_root, W_rel, b, NREG_PAD / 128);

    combine_kernel<<<cdiv(NREGN, 8), 256>>>(out);
}

// round 16
// speedup vs baseline: 1.0710x; 1.0148x over previous
#include <cuda_runtime.h>
#include <cuda_bf16.h>
#include <cuda_fp16.h>
#include <cstdint>

#define NN     100000
#define NE     1600000
#define NREGN  50000
#define NN_PAD 100096   /* 782*128 */
#define NREG_PAD 50048  /* 391*128 */
#define NPATH  4
#define ETAB   200000

// ---------------- scratch (device globals; no allocation allowed) ----------
__device__ __align__(16) __half g_X1h[(size_t)NPATH * NN_PAD * 128];
__device__ __align__(16) __half g_Mh [(size_t)NPATH * NN_PAD * 128];
__device__ __align__(16) __half g_E16[(size_t)ETAB * 128];
__device__ __align__(16) __half g_SEMh[(size_t)NPATH * NREG_PAD * 128];
__device__ int   g_eids32[NPATH * NN];
__device__ int   g_deg[NPATH * NN];
__device__ int   g_rowstart[NPATH * (NN + 1)];
__device__ int   g_cursor[NPATH * NN];
__device__ int   g_col[(size_t)NPATH * NE];
__device__ int   g_bsum[100];
__device__ int   g_boff[100];
__device__ float g_q[512];
__device__ int   g_is64;

// streaming store (evict-first): keeps write streams out of L2 residency
static __device__ __forceinline__ void stcs_u2(void* p, uint2 v) {
    asm volatile("st.global.cs.v2.u32 [%0], {%1, %2};"
                 :: "l"(p), "r"(v.x), "r"(v.y) : "memory");
}

// ---------------- dtype detection (int64 vs int32 edge indices) ------------
__global__ void detect_kernel(const unsigned* __restrict__ ei) {
    __shared__ unsigned sh[256];
    unsigned o = 0;
    for (int i = threadIdx.x; i < 4096; i += 256) o |= ei[2 * i + 1];
    sh[threadIdx.x] = o;
    __syncthreads();
    for (int off = 128; off > 0; off >>= 1) {
        if (threadIdx.x < off) sh[threadIdx.x] |= sh[threadIdx.x + off];
        __syncthreads();
    }
    if (threadIdx.x == 0) g_is64 = (sh[0] == 0u) ? 1 : 0;
}

__device__ __forceinline__ long long load_idx(const void* base, long long i) {
    return g_is64 ? ((const long long*)base)[i]
                  : (long long)((const int*)base)[i];
}

// ---------------- eids -> int32 table + deg zeroing (fused) ----------------
__global__ void conv_eids_kernel(const void* __restrict__ eids) {
    int i = blockIdx.x * 256 + threadIdx.x;
    if (i < NPATH * NN) {
        g_eids32[i] = (int)load_idx(eids, i);
        g_deg[i] = 0;
    }
}

// ---------------- E -> fp16 table ------------------------------------------
__global__ void conv_E_kernel(const float* __restrict__ E) {
    size_t i = (size_t)blockIdx.x * 256 + threadIdx.x;   // 25000*256 = ETAB*32
    float4 v = ((const float4*)E)[i];
    __half2 h0 = __floats2half2_rn(v.x, v.y);
    __half2 h1 = __floats2half2_rn(v.z, v.w);
    uint2 pk;
    pk.x = *(unsigned*)&h0;
    pk.y = *(unsigned*)&h1;
    ((uint2*)g_E16)[i] = pk;
}

// ---------------- CSR build (all paths) ------------------------------------
__global__ void count_all_kernel(const void* __restrict__ ei) {
    long long e = (long long)blockIdx.x * 256 + threadIdx.x; // 25000*256
    int p = (int)(e / NE);
    long long le = e % NE;
    int d = (int)load_idx(ei, ((long long)p * 2 + 1) * NE + le);
    atomicAdd(&g_deg[p * NN + d], 1);
}

#define SBLK 4096
#define BPP  25      /* blocks per path: 25*4096 >= NN */

__global__ void scan_reduce_kernel() {
    int blk = blockIdx.x;              // 100
    int p = blk / BPP, lb = blk % BPP;
    int t = threadIdx.x;               // 256
    int base = lb * SBLK;
    int s = 0;
    for (int i = t; i < SBLK; i += 256) {
        int idx = base + i;
        if (idx < NN) s += g_deg[p * NN + idx];
    }
    __shared__ int sh[256];
    sh[t] = s;
    __syncthreads();
    for (int o = 128; o > 0; o >>= 1) {
        if (t < o) sh[t] += sh[t + o];
        __syncthreads();
    }
    if (t == 0) g_bsum[blk] = sh[0];
}

__global__ void scan_off_kernel() {
    int p = threadIdx.x;
    if (p < NPATH) {
        int run = 0;
        for (int i = 0; i < BPP; i++) {
            g_boff[p * BPP + i] = run;
            run += g_bsum[p * BPP + i];
        }
    }
}

__global__ void scan_write_kernel() {
    int blk = blockIdx.x;
    int p = blk / BPP, lb = blk % BPP;
    int t = threadIdx.x;
    int base = lb * SBLK + t * 16;
    int v[16];
    int s = 0;
#pragma unroll
    for (int i = 0; i < 16; i++) {
        int idx = base + i;
        v[i] = (idx < NN) ? g_deg[p * NN + idx] : 0;
        s += v[i];
    }
    __shared__ int sh[256];
    sh[t] = s;
    __syncthreads();
    for (int o = 1; o < 256; o <<= 1) {
        int u = (t >= o) ? sh[t - o] : 0;
        __syncthreads();
        sh[t] += u;
        __syncthreads();
    }
    int run = g_boff[blk] + sh[t] - s;   // exclusive prefix
#pragma unroll
    for (int i = 0; i < 16; i++) {
        int idx = base + i;
        if (idx < NN) {
            g_rowstart[p * (NN + 1) + idx] = run;
            g_cursor[p * NN + idx] = run;
            run += v[i];
        }
    }
    if (t == 0 && lb == 0) g_rowstart[p * (NN + 1) + NN] = NE;
}

__global__ void scatter_all_kernel(const void* __restrict__ ei) {
    long long e = (long long)blockIdx.x * 256 + threadIdx.x;
    int p = (int)(e / NE);
    long long le = e % NE;
    int s = (int)load_idx(ei, ((long long)p * 2 + 0) * NE + le);
    int d = (int)load_idx(ei, ((long long)p * 2 + 1) * NE + le);
    int pos = atomicAdd(&g_cursor[p * NN + d], 1);
    g_col[(size_t)p * NE + pos] = s;
}

// ---------------- layer-1 mean aggregation (fp16 E rows, all paths) --------
__global__ void agg1_kernel() {
    long long gid = (long long)blockIdx.x * 256 + threadIdx.x;
    long long w = gid >> 5;
    int lane = (int)(gid & 31);
    if (w >= (long long)NPATH * NN) return;
    int p = (int)(w / NN), n = (int)(w % NN);
    __half* Mp = g_Mh + (size_t)p * NN_PAD * 128;
    const int* rs = g_rowstart + p * (NN + 1);
    const int* col = g_col + (size_t)p * NE;
    const int* eid = g_eids32 + p * NN;
    int s = rs[n], e = rs[n + 1];
    int cnt = e - s;
    float x0 = 0.f, x1 = 0.f, x2 = 0.f, x3 = 0.f;
    for (int base = 0; base < cnt; base += 32) {
        int k = base + lane;
        int myEid = 0;
        if (k < cnt) myEid = eid[col[s + k]];
        int m = min(32, cnt - base);
        for (int t = 0; t < m; t++) {
            int ee = __shfl_sync(0xffffffffu, myEid, t);
            uint2 raw = ((const uint2*)(g_E16 + (size_t)ee * 128))[lane];
            float2 a = __half22float2(*(__half2*)&raw.x);
            float2 b = __half22float2(*(__half2*)&raw.y);
            x0 += a.x; x1 += a.y; x2 += b.x; x3 += b.y;
        }
    }
    float inv = 1.f / (float)(cnt > 0 ? cnt : 1);
    __half2 h0 = __floats2half2_rn(x0 * inv, x1 * inv);
    __half2 h1 = __floats2half2_rn(x2 * inv, x3 * inv);
    uint2 pk;
    pk.x = *(unsigned*)&h0;
    pk.y = *(unsigned*)&h1;
    stcs_u2(&((uint2*)Mp)[(size_t)n * 32 + lane], pk);
}

// ---------------- layer-2 mean aggregation (fp16 X1 rows, all paths) -------
__global__ void agg2_kernel() {
    long long gid = (long long)blockIdx.x * 256 + threadIdx.x;
    long long w = gid >> 5;
    int lane = (int)(gid & 31);
    if (w >= (long long)NPATH * NREGN) return;
    int p = (int)(w / NREGN), n = (int)(w % NREGN);
    const __half* Xh = g_X1h + (size_t)p * NN_PAD * 128;
    __half* Mp = g_Mh + (size_t)p * NN_PAD * 128;
    const int* rs = g_rowstart + p * (NN + 1);
    const int* col = g_col + (size_t)p * NE;
    int s = rs[n], e = rs[n + 1];
    int cnt = e - s;
    float x0 = 0.f, x1 = 0.f, x2 = 0.f, x3 = 0.f;
    for (int base = 0; base < cnt; base += 32) {
        int k = base + lane;
        int mySrc = (k < cnt) ? col[s + k] : 0;
        int m = min(32, cnt - base);
        for (int t = 0; t < m; t++) {
            int src = __shfl_sync(0xffffffffu, mySrc, t);
            uint2 raw = ((const uint2*)(Xh + (size_t)src * 128))[lane];
            float2 a = __half22float2(*(__half2*)&raw.x);
            float2 b = __half22float2(*(__half2*)&raw.y);
            x0 += a.x; x1 += a.y; x2 += b.x; x3 += b.y;
        }
    }
    float inv = 1.f / (float)(cnt > 0 ? cnt : 1);
    __half2 h0 = __floats2half2_rn(x0 * inv, x1 * inv);
    __half2 h1 = __floats2half2_rn(x2 * inv, x3 * inv);
    uint2 pk;
    pk.x = *(unsigned*)&h0;
    pk.y = *(unsigned*)&h1;
    stcs_u2(&((uint2*)Mp)[(size_t)n * 32 + lane], pk);
}

// ============ f16 mma GEMM: C = relu([X|M] (Mx256) @ W (256x128) + b) ======
// Single-product f16, A operands stored fp16. Batched: p = blockIdx.x & 3.
// Block tile 128x128, 8 warps in 2(M) x 4(N), warp tile 64x32.
// BK=32 (8 chunks), 4-stage cp.async pipeline (one barrier per chunk),
// ldmatrix A-fragment loads.

#define SM_WH   0                     /* 65536 */
#define SM_A    65536                 /* 4 stages x 10240 (128 rows x 80 B) */
#define SM_BIAS 106496                /* 128 floats */
#define SMEM_TOTAL 107008

#define A_ROW_STRIDE 80

#define CP_ASYNC16(saddr, gptr) \
    asm volatile("cp.async.ca.shared.global [%0], [%1], 16;" \
                 :: "r"(saddr), "l"(gptr))
#define CP_COMMIT() asm volatile("cp.async.commit_group;" ::: "memory")
#define CP_WAIT2()  asm volatile("cp.async.wait_group 2;" ::: "memory")

#define MMA16816F(c, a, b0_, b1_)                                             \
    asm volatile("mma.sync.aligned.m16n8k16.row.col.f32.f16.f16.f32 "         \
        "{%0,%1,%2,%3}, {%4,%5,%6,%7}, {%8,%9}, {%0,%1,%2,%3};"               \
        : "+f"((c)[0]), "+f"((c)[1]), "+f"((c)[2]), "+f"((c)[3])              \
        : "r"((a)[0]), "r"((a)[1]), "r"((a)[2]), "r"((a)[3]),                 \
          "r"(b0_), "r"(b1_))

#define LDSM_X4(r0_, r1_, r2_, r3_, addr)                                     \
    asm volatile("ldmatrix.sync.aligned.m8n8.x4.shared.b16 {%0,%1,%2,%3}, [%4];" \
        : "=r"(r0_), "=r"(r1_), "=r"(r2_), "=r"(r3_) : "r"(addr))

static __device__ __forceinline__ uint32_t smem_u32(const void* p) {
    uint32_t a;
    asm("{ .reg .u64 t; cvta.to.shared.u64 t, %1; cvt.u32.u64 %0, t; }"
        : "=r"(a) : "l"(p));
    return a;
}

// chunks 0..3: root operand rows; chunks 4..7: M rows
static __device__ __forceinline__ void issue_A(uint32_t sbA, int stage,
                                               const __half* __restrict__ Xb0,
                                               const __half* __restrict__ Xb1,
                                               const __half* __restrict__ Mr0,
                                               const __half* __restrict__ Mr1,
                                               int chunk, int tid) {
    const int seg = tid & 3;
    const int off16 = (chunk & 3) * 32 + seg * 8;
    uint32_t sa = sbA + stage * 10240;
    const int ra = tid >> 2;
    {
        const __half* g = (chunk < 4) ? (Xb0 + off16) : (Mr0 + off16);
        CP_ASYNC16(sa + (uint32_t)(ra * A_ROW_STRIDE + seg * 16), g);
    }
    {
        const __half* g = (chunk < 4) ? (Xb1 + off16) : (Mr1 + off16);
        CP_ASYNC16(sa + (uint32_t)((ra + 64) * A_ROW_STRIDE + seg * 16), g);
    }
}

__global__ void __launch_bounds__(256, 1)
gemm_mma_kernel(int layer,
                const float* __restrict__ W_root, const float* __restrict__ W_rel,
                const float* __restrict__ bias_all, int tilesPerPath) {
    extern __shared__ char sm[];
    uint32_t* WH = (uint32_t*)(sm + SM_WH);
    float*    bsm = (float*)(sm + SM_BIAS);
    const uint32_t sbA = smem_u32(sm) + SM_A;
    const int tid = threadIdx.x, lane = tid & 31, wid = tid >> 5;
    const int mrow = (wid & 1) * 64;        // warp M base (2 warps over M)
    const int ncol = (wid >> 1) * 32;       // warp N base (4 warps over N)

    const int p = blockIdx.x & 3;
    const int lcta = blockIdx.x >> 2;
    const int nCta = gridDim.x >> 2;

    const float* B0 = W_root + ((size_t)p * 2 + layer) * 16384;
    const float* B1 = W_rel  + ((size_t)p * 2 + layer) * 16384;
    const float* bias = bias_all + ((size_t)p * 2 + layer) * 128;
    const __half* X1hp = g_X1h + (size_t)p * NN_PAD * 128;
    const __half* Mhp  = g_Mh  + (size_t)p * NN_PAD * 128;
    __half* X1out  = g_X1h + (size_t)p * NN_PAD * 128;
    __half* SEMout = g_SEMh + (size_t)p * NREG_PAD * 128;
    const int* eid = g_eids32 + p * NN;

    // ---- convert weights once into fragment-native f16 layout ----
    for (int i = tid; i < 32768; i += 256) {
        int k = i >> 7, n = i & 127;
        float w = (k < 128) ? B0[i] : B1[i - 16384];
        int off = ((((k >> 4) * 128 + n) * 8 + ((k >> 3) & 1) * 4
                    + ((k >> 1) & 3)) << 2) + (k & 1) * 2;
        *(__half*)(sm + SM_WH + off) = __float2half_rn(w);
    }
    if (tid < 128) bsm[tid] = bias[tid];
    __syncthreads();

    const int ra = tid >> 2;
    const int lrow = ((lane >> 3) & 1) * 8 + (lane & 7);
    const int lcol = (lane >> 4) * 16;   // bytes
    const uint32_t arow_off = (uint32_t)((mrow + lrow) * A_ROW_STRIDE + lcol);

    for (int tile = lcta; tile < tilesPerPath; tile += nCta) {
        const long long r0 = (long long)tile * 128;

        const __half *Xb0, *Xb1;
        if (layer == 0) {
            long long i0 = r0 + ra, i1 = r0 + ra + 64;
            if (i0 >= NN) i0 = NN - 1;
            if (i1 >= NN) i1 = NN - 1;
            Xb0 = g_E16 + (size_t)eid[i0] * 128;
            Xb1 = g_E16 + (size_t)eid[i1] * 128;
        } else {
            Xb0 = X1hp + (r0 + ra) * 128;
            Xb1 = X1hp + (r0 + ra + 64) * 128;
        }
        const __half* Mr0 = Mhp + (r0 + ra) * 128;
        const __half* Mr1 = Mhp + (r0 + ra + 64) * 128;

        float acc[4][4][4];
#pragma unroll
        for (int mf = 0; mf < 4; mf++)
#pragma unroll
            for (int nf = 0; nf < 4; nf++)
#pragma unroll
                for (int j = 0; j < 4; j++) acc[mf][nf][j] = 0.f;

        issue_A(sbA, 0, Xb0, Xb1, Mr0, Mr1, 0, tid); CP_COMMIT();
        issue_A(sbA, 1, Xb0, Xb1, Mr0, Mr1, 1, tid); CP_COMMIT();
        issue_A(sbA, 2, Xb0, Xb1, Mr0, Mr1, 2, tid); CP_COMMIT();

        for (int c = 0; c < 8; c++) {
            CP_WAIT2();
            __syncthreads();        // single barrier: safe with 4 stages
            const uint32_t abase = sbA + (c & 3) * 10240 + arow_off;

#pragma unroll
            for (int ks = 0; ks < 2; ks++) {
                uint32_t a[4][4];
#pragma unroll
                for (int mf = 0; mf < 4; mf++) {
                    LDSM_X4(a[mf][0], a[mf][1], a[mf][2], a[mf][3],
                            abase + mf * 16 * A_ROW_STRIDE + ks * 32);
                }
                const int cb = (c * 2 + ks) * 1024;
#pragma unroll
                for (int nf = 0; nf < 4; nf++) {
                    int bidx = cb + (ncol + nf * 8 + (lane >> 2)) * 8 + (lane & 3);
                    uint32_t bh0 = WH[bidx], bh1 = WH[bidx + 4];
#pragma unroll
                    for (int mf = 0; mf < 4; mf++) {
                        MMA16816F(acc[mf][nf], a[mf], bh0, bh1);
                    }
                }
            }
            if (c + 3 < 8)
                issue_A(sbA, (c + 3) & 3, Xb0, Xb1, Mr0, Mr1, c + 3, tid);
            CP_COMMIT();
        }

        // ---- epilogue: bias + relu; fp16 out both layers ----
        __syncthreads();            // protect stage reuse across tiles
#pragma unroll
        for (int mf = 0; mf < 4; mf++) {
            long long row = r0 + mrow + mf * 16 + (lane >> 2);
#pragma unroll
            for (int nf = 0; nf < 4; nf++) {
                int col = ncol + nf * 8 + (lane & 3) * 2;
                float2 bb = *(const float2*)(bsm + col);
                float2 o0, o1;
                o0.x = fmaxf(acc[mf][nf][0] + bb.x, 0.f);
                o0.y = fmaxf(acc[mf][nf][1] + bb.y, 0.f);
                o1.x = fmaxf(acc[mf][nf][2] + bb.x, 0.f);
                o1.y = fmaxf(acc[mf][nf][3] + bb.y, 0.f);
                __half2 h0 = __floats2half2_rn(o0.x, o0.y);
                __half2 h1 = __floats2half2_rn(o1.x, o1.y);
                __half* dst = (layer == 0) ? X1out : SEMout;
                *(__half2*)(dst + row * 128 + col)       = h0;
                *(__half2*)(dst + (row + 8) * 128 + col) = h1;
            }
        }
    }
}

// ---------------- query = metapath_emb @ Wq + bq ---------------------------
__global__ void query_kernel(const float* __restrict__ me,
                             const float* __restrict__ Wq,
                             const float* __restrict__ bq) {
    int d = threadIdx.x;
#pragma unroll
    for (int p = 0; p < 4; p++) {
        float s = bq[d];
        for (int k = 0; k < 64; k++) s += me[p * 64 + k] * Wq[k * 128 + d];
        g_q[p * 128 + d] = s;
    }
}

// ---------------- semantic attention combine (fp16 sems) -------------------
__global__ void combine_kernel(float* __restrict__ out) {
    int gid = blockIdx.x * 256 + threadIdx.x;
    int w = gid >> 5, lane = gid & 31;
    if (w >= NREGN) return;
    float4 v[4];
    float dots[4];
#pragma unroll
    for (int p = 0; p < 4; p++) {
        uint2 raw = ((const uint2*)(g_SEMh + (size_t)p * NREG_PAD * 128))
                        [(size_t)w * 32 + lane];
        float2 a = __half22float2(*(__half2*)&raw.x);
        float2 b = __half22float2(*(__half2*)&raw.y);
        v[p] = make_float4(a.x, a.y, b.x, b.y);
        float4 qv = ((const float4*)g_q)[p * 32 + lane];
        float dd = v[p].x * qv.x + v[p].y * qv.y + v[p].z * qv.z + v[p].w * qv.w;
#pragma unroll
        for (int o = 16; o > 0; o >>= 1) dd += __shfl_xor_sync(0xffffffffu, dd, o);
        dots[p] = dd * 0.08838834764831845f;
    }
    float mx = fmaxf(fmaxf(dots[0], dots[1]), fmaxf(dots[2], dots[3]));
    float e0 = __expf(dots[0] - mx), e1 = __expf(dots[1] - mx);
    float e2 = __expf(dots[2] - mx), e3 = __expf(dots[3] - mx);
    float inv = 1.f / (e0 + e1 + e2 + e3);
    float4 o;
    o.x = (e0 * v[0].x + e1 * v[1].x + e2 * v[2].x + e3 * v[3].x) * inv;
    o.y = (e0 * v[0].y + e1 * v[1].y + e2 * v[2].y + e3 * v[3].y) * inv;
    o.z = (e0 * v[0].z + e1 * v[1].z + e2 * v[2].z + e3 * v[3].z) * inv;
    o.w = (e0 * v[0].w + e1 * v[1].w + e2 * v[2].w + e3 * v[3].w) * inv;
    ((float4*)out)[(size_t)w * 32 + lane] = o;
}

// ---------------- host orchestration ---------------------------------------
static inline int cdiv(int a, int b) { return (a + b - 1) / b; }

extern "C" void kernel_launch(void* const* d_in, const int* in_sizes, int n_in,
                              void* d_out, int out_size) {
    const float* E       = (const float*)d_in[0];
    const float* me      = (const float*)d_in[1];
    const float* W_root  = (const float*)d_in[2];
    const float* W_rel   = (const float*)d_in[3];
    const float* b       = (const float*)d_in[4];
    const float* Wq      = (const float*)d_in[5];
    const float* bq      = (const float*)d_in[6];
    const void*  ei      = d_in[7];
    const void*  eids    = d_in[8];
    float* out = (float*)d_out;

    cudaFuncSetAttribute(gemm_mma_kernel,
                         cudaFuncAttributeMaxDynamicSharedMemorySize, SMEM_TOTAL);

    detect_kernel<<<1, 256>>>((const unsigned*)ei);
    conv_eids_kernel<<<cdiv(NPATH * NN, 256), 256>>>(eids);
    conv_E_kernel<<<25000, 256>>>(E);
    count_all_kernel<<<NPATH * NE / 256, 256>>>(ei);
    scan_reduce_kernel<<<100, 256>>>();
    scan_off_kernel<<<1, 32>>>();
    scan_write_kernel<<<100, 256>>>();
    scatter_all_kernel<<<NPATH * NE / 256, 256>>>(ei);
    query_kernel<<<1, 128>>>(me, Wq, bq);

    agg1_kernel<<<50000, 256>>>();
    gemm_mma_kernel<<<148, 256, SMEM_TOTAL>>>(0, W_root, W_rel, b, NN_PAD / 128);
    agg2_kernel<<<25000, 256>>>();
    gemm_mma_kernel<<<148, 256, SMEM_TOTAL>>>(1, W_root, W_rel, b, NREG_PAD / 128);

    combine_kernel<<<cdiv(NREGN, 8), 256>>>(out);
}

// round 17
// speedup vs baseline: 1.1103x; 1.0367x over previous
#include <cuda_runtime.h>
#include <cuda_bf16.h>
#include <cuda_fp16.h>
#include <cstdint>

#define NN     100000
#define NE     1600000
#define NREGN  50000
#define NN_PAD 100096   /* 391*256 */
#define SEM_PAD 50176   /* 196*256 */
#define NPATH  4
#define ETAB   200000

// ---------------- scratch (device globals; no allocation allowed) ----------
__device__ __align__(16) __half g_X1h[(size_t)NPATH * NN_PAD * 128];
__device__ __align__(16) __half g_Mh [(size_t)NPATH * NN_PAD * 128];
__device__ __align__(16) __half g_E16[(size_t)ETAB * 128];
__device__ __align__(16) __half g_SEMh[(size_t)NPATH * SEM_PAD * 128];
__device__ int   g_eids32[NPATH * NN];
__device__ int   g_deg[NPATH * NN];
__device__ int   g_rowstart[NPATH * (NN + 1)];
__device__ int   g_cursor[NPATH * NN];
__device__ int   g_col[(size_t)NPATH * NE];
__device__ int   g_bsum[100];
__device__ int   g_cnt;
__device__ float g_q[512];
__device__ int   g_is64;

// streaming store (evict-first)
static __device__ __forceinline__ void stcs_u2(void* p, uint2 v) {
    asm volatile("st.global.cs.v2.u32 [%0], {%1, %2};"
                 :: "l"(p), "r"(v.x), "r"(v.y) : "memory");
}

// ---------------- dtype detection (int64 vs int32 edge indices) ------------
__global__ void detect_kernel(const unsigned* __restrict__ ei) {
    __shared__ unsigned sh[256];
    unsigned o = 0;
    for (int i = threadIdx.x; i < 4096; i += 256) o |= ei[2 * i + 1];
    sh[threadIdx.x] = o;
    __syncthreads();
    for (int off = 128; off > 0; off >>= 1) {
        if (threadIdx.x < off) sh[threadIdx.x] |= sh[threadIdx.x + off];
        __syncthreads();
    }
    if (threadIdx.x == 0) g_is64 = (sh[0] == 0u) ? 1 : 0;
}

__device__ __forceinline__ long long load_idx(const void* base, long long i) {
    return g_is64 ? ((const long long*)base)[i]
                  : (long long)((const int*)base)[i];
}

// ---------------- eids -> int32 + deg zeroing + scan-counter reset ---------
__global__ void conv_eids_kernel(const void* __restrict__ eids) {
    int i = blockIdx.x * 256 + threadIdx.x;
    if (i == 0) g_cnt = 0;
    if (i < NPATH * NN) {
        g_eids32[i] = (int)load_idx(eids, i);
        g_deg[i] = 0;
    }
}

// ---------------- E -> fp16 table ------------------------------------------
__global__ void conv_E_kernel(const float* __restrict__ E) {
    size_t i = (size_t)blockIdx.x * 256 + threadIdx.x;   // ETAB*32
    float4 v = ((const float4*)E)[i];
    __half2 h0 = __floats2half2_rn(v.x, v.y);
    __half2 h1 = __floats2half2_rn(v.z, v.w);
    uint2 pk;
    pk.x = *(unsigned*)&h0;
    pk.y = *(unsigned*)&h1;
    ((uint2*)g_E16)[i] = pk;
}

// ---------------- CSR build ------------------------------------------------
__global__ void count_all_kernel(const void* __restrict__ ei) {
    long long e = (long long)blockIdx.x * 256 + threadIdx.x; // 25000*256
    int p = (int)(e / NE);
    long long le = e % NE;
    int d = (int)load_idx(ei, ((long long)p * 2 + 1) * NE + le);
    atomicAdd(&g_deg[p * NN + d], 1);
}

#define SBLK 4096
#define BPP  25      /* blocks per path: 25*4096 >= NN */

// fused 3-phase scan in ONE launch (100 blocks, all co-resident => safe spin)
__global__ void scan_fused_kernel() {
    int blk = blockIdx.x;              // 100
    int p = blk / BPP, lb = blk % BPP;
    int t = threadIdx.x;               // 256
    int base = lb * SBLK + t * 16;
    int v[16];
    int s = 0;
#pragma unroll
    for (int i = 0; i < 16; i++) {
        int idx = base + i;
        v[i] = (idx < NN) ? g_deg[p * NN + idx] : 0;
        s += v[i];
    }
    __shared__ int sh[256];
    sh[t] = s;
    __syncthreads();
    for (int o = 1; o < 256; o <<= 1) {
        int u = (t >= o) ? sh[t - o] : 0;
        __syncthreads();
        sh[t] += u;
        __syncthreads();
    }
    // publish block total, arrive, spin until all blocks published
    if (t == 0) {
        g_bsum[blk] = sh[255];
        __threadfence();
        atomicAdd(&g_cnt, 1);
        while (*(volatile int*)&g_cnt < 100) { }
        __threadfence();
    }
    __syncthreads();
    __shared__ int off;
    if (t == 0) {
        int run = 0;
        for (int i = 0; i < lb; i++) run += g_bsum[p * BPP + i];
        off = run;
    }
    __syncthreads();
    int run = off + sh[t] - s;           // exclusive prefix
#pragma unroll
    for (int i = 0; i < 16; i++) {
        int idx = base + i;
        if (idx < NN) {
            g_rowstart[p * (NN + 1) + idx] = run;
            g_cursor[p * NN + idx] = run;
            run += v[i];
        }
    }
    if (t == 0 && lb == 0) g_rowstart[p * (NN + 1) + NN] = NE;
}

__global__ void scatter_all_kernel(const void* __restrict__ ei) {
    long long e = (long long)blockIdx.x * 256 + threadIdx.x;
    int p = (int)(e / NE);
    long long le = e % NE;
    int s = (int)load_idx(ei, ((long long)p * 2 + 0) * NE + le);
    int d = (int)load_idx(ei, ((long long)p * 2 + 1) * NE + le);
    int pos = atomicAdd(&g_cursor[p * NN + d], 1);
    g_col[(size_t)p * NE + pos] = s;
}

// ---------------- layer-1 mean aggregation (fp16 E rows, all paths) --------
__global__ void agg1_kernel() {
    long long gid = (long long)blockIdx.x * 256 + threadIdx.x;
    long long w = gid >> 5;
    int lane = (int)(gid & 31);
    if (w >= (long long)NPATH * NN) return;
    int p = (int)(w / NN), n = (int)(w % NN);
    __half* Mp = g_Mh + (size_t)p * NN_PAD * 128;
    const int* rs = g_rowstart + p * (NN + 1);
    const int* col = g_col + (size_t)p * NE;
    const int* eid = g_eids32 + p * NN;
    int s = rs[n], e = rs[n + 1];
    int cnt = e - s;
    float x0 = 0.f, x1 = 0.f, x2 = 0.f, x3 = 0.f;
    for (int base = 0; base < cnt; base += 32) {
        int k = base + lane;
        int myEid = 0;
        if (k < cnt) myEid = eid[col[s + k]];
        int m = min(32, cnt - base);
        for (int t = 0; t < m; t++) {
            int ee = __shfl_sync(0xffffffffu, myEid, t);
            uint2 raw = ((const uint2*)(g_E16 + (size_t)ee * 128))[lane];
            float2 a = __half22float2(*(__half2*)&raw.x);
            float2 b = __half22float2(*(__half2*)&raw.y);
            x0 += a.x; x1 += a.y; x2 += b.x; x3 += b.y;
        }
    }
    float inv = 1.f / (float)(cnt > 0 ? cnt : 1);
    __half2 h0 = __floats2half2_rn(x0 * inv, x1 * inv);
    __half2 h1 = __floats2half2_rn(x2 * inv, x3 * inv);
    uint2 pk;
    pk.x = *(unsigned*)&h0;
    pk.y = *(unsigned*)&h1;
    stcs_u2(&((uint2*)Mp)[(size_t)n * 32 + lane], pk);
}

// ---------------- layer-2 mean aggregation (fp16 X1 rows, all paths) -------
__global__ void agg2_kernel() {
    long long gid = (long long)blockIdx.x * 256 + threadIdx.x;
    long long w = gid >> 5;
    int lane = (int)(gid & 31);
    if (w >= (long long)NPATH * NREGN) return;
    int p = (int)(w / NREGN), n = (int)(w % NREGN);
    const __half* Xh = g_X1h + (size_t)p * NN_PAD * 128;
    __half* Mp = g_Mh + (size_t)p * NN_PAD * 128;
    const int* rs = g_rowstart + p * (NN + 1);
    const int* col = g_col + (size_t)p * NE;
    int s = rs[n], e = rs[n + 1];
    int cnt = e - s;
    float x0 = 0.f, x1 = 0.f, x2 = 0.f, x3 = 0.f;
    for (int base = 0; base < cnt; base += 32) {
        int k = base + lane;
        int mySrc = (k < cnt) ? col[s + k] : 0;
        int m = min(32, cnt - base);
        for (int t = 0; t < m; t++) {
            int src = __shfl_sync(0xffffffffu, mySrc, t);
            uint2 raw = ((const uint2*)(Xh + (size_t)src * 128))[lane];
            float2 a = __half22float2(*(__half2*)&raw.x);
            float2 b = __half22float2(*(__half2*)&raw.y);
            x0 += a.x; x1 += a.y; x2 += b.x; x3 += b.y;
        }
    }
    float inv = 1.f / (float)(cnt > 0 ? cnt : 1);
    __half2 h0 = __floats2half2_rn(x0 * inv, x1 * inv);
    __half2 h1 = __floats2half2_rn(x2 * inv, x3 * inv);
    uint2 pk;
    pk.x = *(unsigned*)&h0;
    pk.y = *(unsigned*)&h1;
    stcs_u2(&((uint2*)Mp)[(size_t)n * 32 + lane], pk);
}

// ============ f16 mma GEMM: C = relu([X|M] (Mx256) @ W (256x128) + b) ======
// Single-product f16, A operands stored fp16. Batched: p = blockIdx.x & 3.
// Block tile 256x128, 512 threads, 16 warps in 4(M) x 4(N), warp tile 64x32.
// BK=32 (8 chunks), 4-stage cp.async pipeline (one barrier per chunk),
// ldmatrix A-fragment loads.

#define SM_WH   0                     /* 65536 */
#define SM_A    65536                 /* 4 stages x 20480 (256 rows x 80 B) */
#define SM_BIAS 147456                /* 128 floats */
#define SMEM_TOTAL 147968

#define A_ROW_STRIDE 80

#define CP_ASYNC16(saddr, gptr) \
    asm volatile("cp.async.ca.shared.global [%0], [%1], 16;" \
                 :: "r"(saddr), "l"(gptr))
#define CP_COMMIT() asm volatile("cp.async.commit_group;" ::: "memory")
#define CP_WAIT2()  asm volatile("cp.async.wait_group 2;" ::: "memory")

#define MMA16816F(c, a, b0_, b1_)                                             \
    asm volatile("mma.sync.aligned.m16n8k16.row.col.f32.f16.f16.f32 "         \
        "{%0,%1,%2,%3}, {%4,%5,%6,%7}, {%8,%9}, {%0,%1,%2,%3};"               \
        : "+f"((c)[0]), "+f"((c)[1]), "+f"((c)[2]), "+f"((c)[3])              \
        : "r"((a)[0]), "r"((a)[1]), "r"((a)[2]), "r"((a)[3]),                 \
          "r"(b0_), "r"(b1_))

#define LDSM_X4(r0_, r1_, r2_, r3_, addr)                                     \
    asm volatile("ldmatrix.sync.aligned.m8n8.x4.shared.b16 {%0,%1,%2,%3}, [%4];" \
        : "=r"(r0_), "=r"(r1_), "=r"(r2_), "=r"(r3_) : "r"(addr))

static __device__ __forceinline__ uint32_t smem_u32(const void* p) {
    uint32_t a;
    asm("{ .reg .u64 t; cvta.to.shared.u64 t, %1; cvt.u32.u64 %0, t; }"
        : "=r"(a) : "l"(p));
    return a;
}

// chunks 0..3: root operand rows; chunks 4..7: M rows
static __device__ __forceinline__ void issue_A(uint32_t sbA, int stage,
                                               const __half* __restrict__ Xb0,
                                               const __half* __restrict__ Xb1,
                                               const __half* __restrict__ Mr0,
                                               const __half* __restrict__ Mr1,
                                               int chunk, int tid) {
    const int seg = tid & 3;
    const int off16 = (chunk & 3) * 32 + seg * 8;
    uint32_t sa = sbA + stage * 20480;
    const int ra = tid >> 2;                 // 0..127
    {
        const __half* g = (chunk < 4) ? (Xb0 + off16) : (Mr0 + off16);
        CP_ASYNC16(sa + (uint32_t)(ra * A_ROW_STRIDE + seg * 16), g);
    }
    {
        const __half* g = (chunk < 4) ? (Xb1 + off16) : (Mr1 + off16);
        CP_ASYNC16(sa + (uint32_t)((ra + 128) * A_ROW_STRIDE + seg * 16), g);
    }
}

__global__ void __launch_bounds__(512, 1)
gemm_mma_kernel(int layer,
                const float* __restrict__ W_root, const float* __restrict__ W_rel,
                const float* __restrict__ bias_all, int tilesPerPath) {
    extern __shared__ char sm[];
    uint32_t* WH = (uint32_t*)(sm + SM_WH);
    float*    bsm = (float*)(sm + SM_BIAS);
    const uint32_t sbA = smem_u32(sm) + SM_A;
    const int tid = threadIdx.x, lane = tid & 31, wid = tid >> 5;
    const int mrow = (wid & 3) * 64;        // 4 warps over M (256)
    const int ncol = (wid >> 2) * 32;       // 4 warps over N (128)

    const int p = blockIdx.x & 3;
    const int lcta = blockIdx.x >> 2;
    const int nCta = gridDim.x >> 2;

    const float* B0 = W_root + ((size_t)p * 2 + layer) * 16384;
    const float* B1 = W_rel  + ((size_t)p * 2 + layer) * 16384;
    const float* bias = bias_all + ((size_t)p * 2 + layer) * 128;
    const __half* X1hp = g_X1h + (size_t)p * NN_PAD * 128;
    const __half* Mhp  = g_Mh  + (size_t)p * NN_PAD * 128;
    __half* X1out  = g_X1h + (size_t)p * NN_PAD * 128;
    __half* SEMout = g_SEMh + (size_t)p * SEM_PAD * 128;
    const int* eid = g_eids32 + p * NN;

    // ---- convert weights once into fragment-native f16 layout ----
    for (int i = tid; i < 32768; i += 512) {
        int k = i >> 7, n = i & 127;
        float w = (k < 128) ? B0[i] : B1[i - 16384];
        int off = ((((k >> 4) * 128 + n) * 8 + ((k >> 3) & 1) * 4
                    + ((k >> 1) & 3)) << 2) + (k & 1) * 2;
        *(__half*)(sm + SM_WH + off) = __float2half_rn(w);
    }
    if (tid < 128) bsm[tid] = bias[tid];
    __syncthreads();

    const int ra = tid >> 2;
    const int lrow = ((lane >> 3) & 1) * 8 + (lane & 7);
    const int lcol = (lane >> 4) * 16;   // bytes
    const uint32_t arow_off = (uint32_t)((mrow + lrow) * A_ROW_STRIDE + lcol);

    for (int tile = lcta; tile < tilesPerPath; tile += nCta) {
        const long long r0 = (long long)tile * 256;

        const __half *Xb0, *Xb1;
        if (layer == 0) {
            long long i0 = r0 + ra, i1 = r0 + ra + 128;
            if (i0 >= NN) i0 = NN - 1;
            if (i1 >= NN) i1 = NN - 1;
            Xb0 = g_E16 + (size_t)eid[i0] * 128;
            Xb1 = g_E16 + (size_t)eid[i1] * 128;
        } else {
            Xb0 = X1hp + (r0 + ra) * 128;
            Xb1 = X1hp + (r0 + ra + 128) * 128;
        }
        const __half* Mr0 = Mhp + (r0 + ra) * 128;
        const __half* Mr1 = Mhp + (r0 + ra + 128) * 128;

        float acc[4][4][4];
#pragma unroll
        for (int mf = 0; mf < 4; mf++)
#pragma unroll
            for (int nf = 0; nf < 4; nf++)
#pragma unroll
                for (int j = 0; j < 4; j++) acc[mf][nf][j] = 0.f;

        issue_A(sbA, 0, Xb0, Xb1, Mr0, Mr1, 0, tid); CP_COMMIT();
        issue_A(sbA, 1, Xb0, Xb1, Mr0, Mr1, 1, tid); CP_COMMIT();
        issue_A(sbA, 2, Xb0, Xb1, Mr0, Mr1, 2, tid); CP_COMMIT();

        for (int c = 0; c < 8; c++) {
            CP_WAIT2();
            __syncthreads();        // single barrier: safe with 4 stages
            const uint32_t abase = sbA + (c & 3) * 20480 + arow_off;

#pragma unroll
            for (int ks = 0; ks < 2; ks++) {
                uint32_t a[4][4];
#pragma unroll
                for (int mf = 0; mf < 4; mf++) {
                    LDSM_X4(a[mf][0], a[mf][1], a[mf][2], a[mf][3],
                            abase + mf * 16 * A_ROW_STRIDE + ks * 32);
                }
                const int cb = (c * 2 + ks) * 1024;
#pragma unroll
                for (int nf = 0; nf < 4; nf++) {
                    int bidx = cb + (ncol + nf * 8 + (lane >> 2)) * 8 + (lane & 3);
                    uint32_t bh0 = WH[bidx], bh1 = WH[bidx + 4];
#pragma unroll
                    for (int mf = 0; mf < 4; mf++) {
                        MMA16816F(acc[mf][nf], a[mf], bh0, bh1);
                    }
                }
            }
            if (c + 3 < 8)
                issue_A(sbA, (c + 3) & 3, Xb0, Xb1, Mr0, Mr1, c + 3, tid);
            CP_COMMIT();
        }

        // ---- epilogue: bias + relu; fp16 out both layers ----
        __syncthreads();            // protect stage reuse across tiles
#pragma unroll
        for (int mf = 0; mf < 4; mf++) {
            long long row = r0 + mrow + mf * 16 + (lane >> 2);
#pragma unroll
            for (int nf = 0; nf < 4; nf++) {
                int col = ncol + nf * 8 + (lane & 3) * 2;
                float2 bb = *(const float2*)(bsm + col);
                float2 o0, o1;
                o0.x = fmaxf(acc[mf][nf][0] + bb.x, 0.f);
                o0.y = fmaxf(acc[mf][nf][1] + bb.y, 0.f);
                o1.x = fmaxf(acc[mf][nf][2] + bb.x, 0.f);
                o1.y = fmaxf(acc[mf][nf][3] + bb.y, 0.f);
                __half2 h0 = __floats2half2_rn(o0.x, o0.y);
                __half2 h1 = __floats2half2_rn(o1.x, o1.y);
                __half* dst = (layer == 0) ? X1out : SEMout;
                *(__half2*)(dst + row * 128 + col)       = h0;
                *(__half2*)(dst + (row + 8) * 128 + col) = h1;
            }
        }
    }
}

// ---------------- query = metapath_emb @ Wq + bq ---------------------------
__global__ void query_kernel(const float* __restrict__ me,
                             const float* __restrict__ Wq,
                             const float* __restrict__ bq) {
    int d = threadIdx.x;
#pragma unroll
    for (int p = 0; p < 4; p++) {
        float s = bq[d];
        for (int k = 0; k < 64; k++) s += me[p * 64 + k] * Wq[k * 128 + d];
        g_q[p * 128 + d] = s;
    }
}

// ---------------- semantic attention combine (fp16 sems) -------------------
__global__ void combine_kernel(float* __restrict__ out) {
    int gid = blockIdx.x * 256 + threadIdx.x;
    int w = gid >> 5, lane = gid & 31;
    if (w >= NREGN) return;
    float4 v[4];
    float dots[4];
#pragma unroll
    for (int p = 0; p < 4; p++) {
        uint2 raw = ((const uint2*)(g_SEMh + (size_t)p * SEM_PAD * 128))
                        [(size_t)w * 32 + lane];
        float2 a = __half22float2(*(__half2*)&raw.x);
        float2 b = __half22float2(*(__half2*)&raw.y);
        v[p] = make_float4(a.x, a.y, b.x, b.y);
        float4 qv = ((const float4*)g_q)[p * 32 + lane];
        float dd = v[p].x * qv.x + v[p].y * qv.y + v[p].z * qv.z + v[p].w * qv.w;
#pragma unroll
        for (int o = 16; o > 0; o >>= 1) dd += __shfl_xor_sync(0xffffffffu, dd, o);
        dots[p] = dd * 0.08838834764831845f;
    }
    float mx = fmaxf(fmaxf(dots[0], dots[1]), fmaxf(dots[2], dots[3]));
    float e0 = __expf(dots[0] - mx), e1 = __expf(dots[1] - mx);
    float e2 = __expf(dots[2] - mx), e3 = __expf(dots[3] - mx);
    float inv = 1.f / (e0 + e1 + e2 + e3);
    float4 o;
    o.x = (e0 * v[0].x + e1 * v[1].x + e2 * v[2].x + e3 * v[3].x) * inv;
    o.y = (e0 * v[0].y + e1 * v[1].y + e2 * v[2].y + e3 * v[3].y) * inv;
    o.z = (e0 * v[0].z + e1 * v[1].z + e2 * v[2].z + e3 * v[3].z) * inv;
    o.w = (e0 * v[0].w + e1 * v[1].w + e2 * v[2].w + e3 * v[3].w) * inv;
    ((float4*)out)[(size_t)w * 32 + lane] = o;
}

// ---------------- host orchestration ---------------------------------------
static inline int cdiv(int a, int b) { return (a + b - 1) / b; }

extern "C" void kernel_launch(void* const* d_in, const int* in_sizes, int n_in,
                              void* d_out, int out_size) {
    const float* E       = (const float*)d_in[0];
    const float* me      = (const float*)d_in[1];
    const float* W_root  = (const float*)d_in[2];
    const float* W_rel   = (const float*)d_in[3];
    const float* b       = (const float*)d_in[4];
    const float* Wq      = (const float*)d_in[5];
    const float* bq      = (const float*)d_in[6];
    const void*  ei      = d_in[7];
    const void*  eids    = d_in[8];
    float* out = (float*)d_out;

    cudaFuncSetAttribute(gemm_mma_kernel,
                         cudaFuncAttributeMaxDynamicSharedMemorySize, SMEM_TOTAL);

    detect_kernel<<<1, 256>>>((const unsigned*)ei);
    conv_eids_kernel<<<cdiv(NPATH * NN, 256), 256>>>(eids);
    conv_E_kernel<<<25000, 256>>>(E);
    count_all_kernel<<<NPATH * NE / 256, 256>>>(ei);
    scan_fused_kernel<<<100, 256>>>();
    scatter_all_kernel<<<NPATH * NE / 256, 256>>>(ei);
    query_kernel<<<1, 128>>>(me, Wq, bq);

    agg1_kernel<<<50000, 256>>>();
    gemm_mma_kernel<<<148, 512, SMEM_TOTAL>>>(0, W_root, W_rel, b, NN_PAD / 256);
    agg2_kernel<<<25000, 256>>>();
    gemm_mma_kernel<<<148, 512, SMEM_TOTAL>>>(1, W_root, W_rel, b, SEM_PAD / 256);

    combine_kernel<<<cdiv(NREGN, 8), 256>>>(out);
}